// round 1
// baseline (speedup 1.0000x reference)
#include <cuda_runtime.h>
#include <math.h>

// Problem constants (L = 1 collapses the Mamba scan — see analysis)
#define BB      512
#define DMODEL  512
#define DSTATE  128
#define DINNER  1024
#define DTRANK  32
#define HIDDEN  256
#define XDBL_W  (DTRANK + 2*DSTATE)   // 288

// -------- scratch (no allocations allowed; __device__ globals) --------
__device__ float g_xin [BB*DINNER];   // silu(conv(x_in))
__device__ float g_zsil[BB*DINNER];   // silu(z)
__device__ float g_xdbl[BB*XDBL_W];   // [dt | Bm | Cm]
__device__ float g_bc  [BB];          // dot(Bm, Cm)
__device__ float g_y   [BB*DINNER];
__device__ float g_out1[BB*DMODEL];
__device__ float g_h1  [BB*HIDDEN];

__device__ __forceinline__ float siluf(float x) { return x / (1.f + __expf(-x)); }

// ---------------------------------------------------------------------
// Generic C[M,N] = A[M,K] @ W[N,K]^T  (row-major, K-major both sides)
// BM=BN=64, BK=16, 256 threads, 4x4 per thread.
// MODE 0: plain store
// MODE 1: + bias(aux0), leaky-relu 0.1
// MODE 2: in_proj split: n<DINNER -> xin = silu(conv_b + conv_w[:,1]*acc)
//         else            zsil = silu(acc)        (C=g_xin, out2=g_zsil)
// MODE 3: dt = softplus(acc + aux0[n]); y = (dt*xin*bc + D[n]*xin)*zsil
// ---------------------------------------------------------------------
template<int MODE>
__global__ void __launch_bounds__(256)
gemm_nt(const float* __restrict__ A, int lda,
        const float* __restrict__ W,
        float* __restrict__ C,
        int N, int K,
        const float* __restrict__ aux0,
        const float* __restrict__ aux1,
        float* __restrict__ out2)
{
    __shared__ float As[16][64];
    __shared__ float Ws[16][64];

    const int tid = threadIdx.x;
    const int tx  = tid & 15;        // 0..15 -> n
    const int ty  = tid >> 4;        // 0..15 -> m
    const int m0  = blockIdx.y * 64;
    const int n0  = blockIdx.x * 64;

    const int lrow = tid >> 2;       // 0..63
    const int lcol = (tid & 3) * 4;  // 0,4,8,12

    float acc[4][4] = {};

    for (int k0 = 0; k0 < K; k0 += 16) {
        // A tile (M=512 always divisible by 64: no m guard)
        float4 av = *reinterpret_cast<const float4*>(&A[(m0 + lrow)*lda + k0 + lcol]);
        As[lcol+0][lrow] = av.x; As[lcol+1][lrow] = av.y;
        As[lcol+2][lrow] = av.z; As[lcol+3][lrow] = av.w;

        // W tile with N guard (N=288 case)
        const int wrow = n0 + lrow;
        float4 wv = make_float4(0.f, 0.f, 0.f, 0.f);
        if (wrow < N)
            wv = *reinterpret_cast<const float4*>(&W[wrow*K + k0 + lcol]);
        Ws[lcol+0][lrow] = wv.x; Ws[lcol+1][lrow] = wv.y;
        Ws[lcol+2][lrow] = wv.z; Ws[lcol+3][lrow] = wv.w;

        __syncthreads();

        #pragma unroll
        for (int k = 0; k < 16; k++) {
            float4 a = *reinterpret_cast<const float4*>(&As[k][ty*4]);
            float4 w = *reinterpret_cast<const float4*>(&Ws[k][tx*4]);
            acc[0][0] += a.x*w.x; acc[0][1] += a.x*w.y; acc[0][2] += a.x*w.z; acc[0][3] += a.x*w.w;
            acc[1][0] += a.y*w.x; acc[1][1] += a.y*w.y; acc[1][2] += a.y*w.z; acc[1][3] += a.y*w.w;
            acc[2][0] += a.z*w.x; acc[2][1] += a.z*w.y; acc[2][2] += a.z*w.z; acc[2][3] += a.z*w.w;
            acc[3][0] += a.w*w.x; acc[3][1] += a.w*w.y; acc[3][2] += a.w*w.z; acc[3][3] += a.w*w.w;
        }
        __syncthreads();
    }

    #pragma unroll
    for (int i = 0; i < 4; i++) {
        const int m = m0 + ty*4 + i;
        #pragma unroll
        for (int j = 0; j < 4; j++) {
            const int n = n0 + tx*4 + j;
            if (n >= N) continue;
            float v = acc[i][j];
            if (MODE == 0) {
                C[m*N + n] = v;
            } else if (MODE == 1) {
                v += aux0[n];
                C[m*N + n] = (v >= 0.f) ? v : 0.1f*v;
            } else if (MODE == 2) {
                if (n < DINNER) {
                    float cv = aux0[n] + aux1[2*n + 1] * v;   // conv_b + conv_w[:,1]*x
                    C[m*DINNER + n] = siluf(cv);
                } else {
                    out2[m*DINNER + (n - DINNER)] = siluf(v);
                }
            } else { // MODE 3
                v += aux0[n];                                  // dt_proj_b
                float dt = (v > 20.f) ? v : log1pf(__expf(v)); // softplus
                float xv = g_xin[m*DINNER + n];
                C[m*DINNER + n] =
                    (dt * xv * g_bc[m] + aux1[n] * xv) * g_zsil[m*DINNER + n];
            }
        }
    }
}

// bc[b] = dot(Bm[b], Cm[b]) over 128 states
__global__ void bc_kernel()
{
    const int b = blockIdx.x;
    const int t = threadIdx.x;  // 128
    float v = g_xdbl[b*XDBL_W + DTRANK + t] *
              g_xdbl[b*XDBL_W + DTRANK + DSTATE + t];
    #pragma unroll
    for (int o = 16; o > 0; o >>= 1) v += __shfl_xor_sync(0xFFFFFFFFu, v, o);
    __shared__ float ws[4];
    if ((t & 31) == 0) ws[t >> 5] = v;
    __syncthreads();
    if (t == 0) g_bc[b] = ws[0] + ws[1] + ws[2] + ws[3];
}

// out[b] = sigmoid( dot(h1[b], fc5_w) + fc5_b )
__global__ void fc5_kernel(const float* __restrict__ w,
                           const float* __restrict__ bias,
                           float* __restrict__ out)
{
    const int b = blockIdx.x;
    const int t = threadIdx.x;  // 256
    float v = g_h1[b*HIDDEN + t] * w[t];
    #pragma unroll
    for (int o = 16; o > 0; o >>= 1) v += __shfl_xor_sync(0xFFFFFFFFu, v, o);
    __shared__ float ws[8];
    if ((t & 31) == 0) ws[t >> 5] = v;
    __syncthreads();
    if (t == 0) {
        float s = bias[0];
        #pragma unroll
        for (int i = 0; i < 8; i++) s += ws[i];
        out[b] = 1.f / (1.f + __expf(-s));
    }
}

extern "C" void kernel_launch(void* const* d_in, const int* in_sizes, int n_in,
                              void* d_out, int out_size)
{
    const float* x         = (const float*)d_in[0];
    const float* in_proj_w = (const float*)d_in[1];
    const float* conv_w    = (const float*)d_in[2];
    const float* conv_b    = (const float*)d_in[3];
    const float* x_proj_w  = (const float*)d_in[4];
    const float* dt_proj_w = (const float*)d_in[5];
    const float* dt_proj_b = (const float*)d_in[6];
    // d_in[7] = A_log: dead (h0 = 0, L = 1)
    const float* Dp        = (const float*)d_in[8];
    const float* out_projw = (const float*)d_in[9];
    const float* fc1_w     = (const float*)d_in[10];
    const float* fc1_b     = (const float*)d_in[11];
    const float* fc5_w     = (const float*)d_in[12];
    const float* fc5_b     = (const float*)d_in[13];
    float* out = (float*)d_out;

    float *xin, *zsil, *xdbl, *y, *out1, *h1;
    cudaGetSymbolAddress((void**)&xin,  g_xin);
    cudaGetSymbolAddress((void**)&zsil, g_zsil);
    cudaGetSymbolAddress((void**)&xdbl, g_xdbl);
    cudaGetSymbolAddress((void**)&y,    g_y);
    cudaGetSymbolAddress((void**)&out1, g_out1);
    cudaGetSymbolAddress((void**)&h1,   g_h1);

    const dim3 blk(256);
    // 1. in_proj (N=2048,K=512) fused conv+silu split -> xin, zsil
    gemm_nt<2><<<dim3(2048/64, BB/64), blk>>>(x, DMODEL, in_proj_w, xin,
                                              2*DINNER, DMODEL, conv_b, conv_w, zsil);
    // 2. x_proj (N=288,K=1024) -> xdbl
    gemm_nt<0><<<dim3((XDBL_W + 63)/64, BB/64), blk>>>(xin, DINNER, x_proj_w, xdbl,
                                                       XDBL_W, DINNER, nullptr, nullptr, nullptr);
    // 3. bc[b] = Bm . Cm
    bc_kernel<<<BB, 128>>>();
    // 4. dt_proj (N=1024,K=32, lda=288) + softplus + y formation -> y
    gemm_nt<3><<<dim3(DINNER/64, BB/64), blk>>>(xdbl, XDBL_W, dt_proj_w, y,
                                                DINNER, DTRANK, dt_proj_b, Dp, nullptr);
    // 5. out_proj (N=512,K=1024) -> out1
    gemm_nt<0><<<dim3(DMODEL/64, BB/64), blk>>>(y, DINNER, out_projw, out1,
                                                DMODEL, DINNER, nullptr, nullptr, nullptr);
    // 6. fc1 (N=256,K=512) + bias + leaky -> h1
    gemm_nt<1><<<dim3(HIDDEN/64, BB/64), blk>>>(out1, DMODEL, fc1_w, h1,
                                                HIDDEN, DMODEL, fc1_b, nullptr, nullptr);
    // 7. fc5 + sigmoid -> out (B,1)
    fc5_kernel<<<BB, 256>>>(fc5_w, fc5_b, out);
}

// round 2
// speedup vs baseline: 2.0491x; 2.0491x over previous
#include <cuda_runtime.h>
#include <math.h>

// L = 1 collapses the Mamba scan: h = dBu, y = dt*xin*(Bm.Cm) + D*xin, A_log dead.
#define BB      512
#define DMODEL  512
#define DSTATE  128
#define DINNER  1024
#define DTRANK  32
#define HIDDEN  256
#define XDBL_W  (DTRANK + 2*DSTATE)   // 288

// -------- scratch (no allocations allowed; __device__ globals) --------
__device__ float g_xin [BB*DINNER];
__device__ float g_zsil[BB*DINNER];
__device__ float g_xdbl[BB*XDBL_W];
__device__ float g_bc  [BB];
__device__ float g_y   [BB*DINNER];
__device__ float g_out1[BB*DMODEL];
__device__ float g_h1  [BB*HIDDEN];

__device__ __forceinline__ float siluf(float x) { return x / (1.f + __expf(-x)); }

__device__ __forceinline__ unsigned f2tf32(float f) {
    unsigned u;
    asm("cvt.rna.tf32.f32 %0, %1;" : "=r"(u) : "f"(f));
    return u;
}

__device__ __forceinline__ void mma_tf32(float c[4],
                                         unsigned a0, unsigned a1, unsigned a2, unsigned a3,
                                         unsigned b0, unsigned b1)
{
    asm volatile(
        "mma.sync.aligned.m16n8k8.row.col.f32.tf32.tf32.f32 "
        "{%0,%1,%2,%3}, {%4,%5,%6,%7}, {%8,%9}, {%0,%1,%2,%3};"
        : "+f"(c[0]), "+f"(c[1]), "+f"(c[2]), "+f"(c[3])
        : "r"(a0), "r"(a1), "r"(a2), "r"(a3), "r"(b0), "r"(b1));
}

// ---------------------------------------------------------------------
// Tensor-core GEMM: C[M,N] = A[M,K] @ W[N,K]^T, tf32 mma, fp32 accum.
// BM=64, BK=32, BN in {32,64}. 256 threads = 8 warps (4 m x 2 n).
// Warp tile: 16 x (BN/2). NT = BN/16 n-subtiles of m16n8 per warp.
// Requires: M % 64 == 0, N % BN == 0, K % 32 == 0 (all shapes satisfy this).
// MODE 0: plain store
// MODE 1: + bias(aux0), leaky-relu 0.1
// MODE 2: in_proj split: n<DINNER -> xin = silu(conv_b + conv_w[:,1]*v)
//         else            zsil = silu(v)
// MODE 3: dt = softplus(v + aux0[n]); C = (dt*xin*bc + aux1[n]*xin)*zsil
// ---------------------------------------------------------------------
template<int MODE, int BN>
__global__ void __launch_bounds__(256)
gemm_tc(const float* __restrict__ A, int lda,
        const float* __restrict__ W,
        float* __restrict__ C,
        int N, int K,
        const float* __restrict__ aux0,
        const float* __restrict__ aux1,
        float* __restrict__ out2)
{
    constexpr int BM  = 64;
    constexpr int BK  = 32;
    constexpr int LDS = 36;          // stride pad: conflict-free frags, 16B aligned
    constexpr int NT  = BN / 16;     // m16n8 tiles per warp along n
    constexpr int AIT = (BM * (BK/4)) / 256;   // float4 loads per thread for A
    constexpr int WIT = (BN * (BK/4)) / 256;   // for W (1 when BN=32)

    __shared__ unsigned As[BM][LDS];
    __shared__ unsigned Ws[BN][LDS];

    const int tid  = threadIdx.x;
    const int lane = tid & 31;
    const int wid  = tid >> 5;
    const int wm   = wid >> 1;       // 0..3
    const int wn   = wid & 1;        // 0..1
    const int g    = lane >> 2;      // 0..7
    const int t    = lane & 3;       // 0..3
    const int m0   = blockIdx.y * BM;
    const int n0   = blockIdx.x * BN;

    float acc[NT][4] = {};

    for (int k0 = 0; k0 < K; k0 += BK) {
        // ---- load A tile (BM x BK) as tf32 ----
        #pragma unroll
        for (int it = 0; it < AIT; ++it) {
            int idx = tid + it * 256;
            int r = idx >> 3, cv = (idx & 7) * 4;
            float4 v = *reinterpret_cast<const float4*>(&A[(m0 + r) * lda + k0 + cv]);
            *reinterpret_cast<uint4*>(&As[r][cv]) =
                make_uint4(f2tf32(v.x), f2tf32(v.y), f2tf32(v.z), f2tf32(v.w));
        }
        // ---- load W tile (BN x BK) as tf32 ----
        #pragma unroll
        for (int it = 0; it < WIT; ++it) {
            int idx = tid + it * 256;
            if (WIT * 256 > BN * (BK/4) && idx >= BN * (BK/4)) break;
            int r = idx >> 3, cv = (idx & 7) * 4;
            float4 v = *reinterpret_cast<const float4*>(&W[(n0 + r) * K + k0 + cv]);
            *reinterpret_cast<uint4*>(&Ws[r][cv]) =
                make_uint4(f2tf32(v.x), f2tf32(v.y), f2tf32(v.z), f2tf32(v.w));
        }
        __syncthreads();

        #pragma unroll
        for (int ks = 0; ks < BK / 8; ++ks) {
            const int kk  = ks * 8 + t;
            const int ar  = wm * 16 + g;
            unsigned a0 = As[ar    ][kk];
            unsigned a1 = As[ar + 8][kk];
            unsigned a2 = As[ar    ][kk + 4];
            unsigned a3 = As[ar + 8][kk + 4];
            #pragma unroll
            for (int j = 0; j < NT; ++j) {
                const int br = wn * (BN / 2) + j * 8 + g;
                unsigned b0 = Ws[br][kk];
                unsigned b1 = Ws[br][kk + 4];
                mma_tf32(acc[j], a0, a1, a2, a3, b0, b1);
            }
        }
        __syncthreads();
    }

    // ---- epilogue: c0:(m,n) c1:(m,n+1) c2:(m+8,n) c3:(m+8,n+1) ----
    #pragma unroll
    for (int j = 0; j < NT; ++j) {
        const int nb = n0 + wn * (BN / 2) + j * 8 + 2 * t;
        const int mb = m0 + wm * 16 + g;
        #pragma unroll
        for (int e = 0; e < 4; ++e) {
            const int m = mb + (e >> 1) * 8;
            const int n = nb + (e & 1);
            float v = acc[j][e];
            if (MODE == 0) {
                C[m * N + n] = v;
            } else if (MODE == 1) {
                v += aux0[n];
                C[m * N + n] = (v >= 0.f) ? v : 0.1f * v;
            } else if (MODE == 2) {
                if (n < DINNER) {
                    float cv = aux0[n] + aux1[2 * n + 1] * v;   // conv_b + conv_w[:,1]*x
                    C[m * DINNER + n] = siluf(cv);
                } else {
                    out2[m * DINNER + (n - DINNER)] = siluf(v);
                }
            } else { // MODE 3
                v += aux0[n];                                   // dt_proj_b
                float dt = (v > 20.f) ? v : log1pf(__expf(v));  // softplus
                float xv = g_xin[m * DINNER + n];
                C[m * DINNER + n] =
                    (dt * xv * g_bc[m] + aux1[n] * xv) * g_zsil[m * DINNER + n];
            }
        }
    }
}

// bc[b] = dot(Bm[b], Cm[b]) over 128 states
__global__ void bc_kernel()
{
    const int b = blockIdx.x;
    const int t = threadIdx.x;  // 128
    float v = g_xdbl[b * XDBL_W + DTRANK + t] *
              g_xdbl[b * XDBL_W + DTRANK + DSTATE + t];
    #pragma unroll
    for (int o = 16; o > 0; o >>= 1) v += __shfl_xor_sync(0xFFFFFFFFu, v, o);
    __shared__ float ws[4];
    if ((t & 31) == 0) ws[t >> 5] = v;
    __syncthreads();
    if (t == 0) g_bc[b] = ws[0] + ws[1] + ws[2] + ws[3];
}

// out[b] = sigmoid( dot(h1[b], fc5_w) + fc5_b )
__global__ void fc5_kernel(const float* __restrict__ w,
                           const float* __restrict__ bias,
                           float* __restrict__ out)
{
    const int b = blockIdx.x;
    const int t = threadIdx.x;  // 256
    float v = g_h1[b * HIDDEN + t] * w[t];
    #pragma unroll
    for (int o = 16; o > 0; o >>= 1) v += __shfl_xor_sync(0xFFFFFFFFu, v, o);
    __shared__ float ws[8];
    if ((t & 31) == 0) ws[t >> 5] = v;
    __syncthreads();
    if (t == 0) {
        float s = bias[0];
        #pragma unroll
        for (int i = 0; i < 8; i++) s += ws[i];
        out[b] = 1.f / (1.f + __expf(-s));
    }
}

extern "C" void kernel_launch(void* const* d_in, const int* in_sizes, int n_in,
                              void* d_out, int out_size)
{
    const float* x         = (const float*)d_in[0];
    const float* in_proj_w = (const float*)d_in[1];
    const float* conv_w    = (const float*)d_in[2];
    const float* conv_b    = (const float*)d_in[3];
    const float* x_proj_w  = (const float*)d_in[4];
    const float* dt_proj_w = (const float*)d_in[5];
    const float* dt_proj_b = (const float*)d_in[6];
    // d_in[7] = A_log: dead (h0 = 0, L = 1)
    const float* Dp        = (const float*)d_in[8];
    const float* out_projw = (const float*)d_in[9];
    const float* fc1_w     = (const float*)d_in[10];
    const float* fc1_b     = (const float*)d_in[11];
    const float* fc5_w     = (const float*)d_in[12];
    const float* fc5_b     = (const float*)d_in[13];
    float* out = (float*)d_out;

    float *xin, *zsil, *xdbl, *y, *out1, *h1;
    cudaGetSymbolAddress((void**)&xin,  g_xin);
    cudaGetSymbolAddress((void**)&zsil, g_zsil);
    cudaGetSymbolAddress((void**)&xdbl, g_xdbl);
    cudaGetSymbolAddress((void**)&y,    g_y);
    cudaGetSymbolAddress((void**)&out1, g_out1);
    cudaGetSymbolAddress((void**)&h1,   g_h1);

    const dim3 blk(256);
    // 1. in_proj (N=2048,K=512) fused conv+silu split -> xin, zsil   [grid 32x8]
    gemm_tc<2, 64><<<dim3(2048/64, BB/64), blk>>>(x, DMODEL, in_proj_w, xin,
                                                  2*DINNER, DMODEL, conv_b, conv_w, zsil);
    // 2. x_proj (N=288,K=1024) -> xdbl                               [grid 9x8]
    gemm_tc<0, 32><<<dim3(XDBL_W/32, BB/64), blk>>>(xin, DINNER, x_proj_w, xdbl,
                                                    XDBL_W, DINNER, nullptr, nullptr, nullptr);
    // 3. bc[b] = Bm . Cm
    bc_kernel<<<BB, 128>>>();
    // 4. dt_proj (N=1024,K=32,lda=288) + softplus + y                [grid 16x8]
    gemm_tc<3, 64><<<dim3(DINNER/64, BB/64), blk>>>(xdbl, XDBL_W, dt_proj_w, y,
                                                    DINNER, DTRANK, dt_proj_b, Dp, nullptr);
    // 5. out_proj (N=512,K=1024) -> out1                             [grid 16x8]
    gemm_tc<0, 32><<<dim3(DMODEL/32, BB/64), blk>>>(y, DINNER, out_projw, out1,
                                                    DMODEL, DINNER, nullptr, nullptr, nullptr);
    // 6. fc1 (N=256,K=512) + bias + leaky -> h1                      [grid 8x8]
    gemm_tc<1, 32><<<dim3(HIDDEN/32, BB/64), blk>>>(out1, DMODEL, fc1_w, h1,
                                                    HIDDEN, DMODEL, fc1_b, nullptr, nullptr);
    // 7. fc5 + sigmoid -> out (B,1)
    fc5_kernel<<<BB, 256>>>(fc5_w, fc5_b, out);
}

// round 3
// speedup vs baseline: 3.6686x; 1.7904x over previous
#include <cuda_runtime.h>
#include <math.h>
#include <stdint.h>

// L = 1 collapses the Mamba scan: h = dBu, y = dt*xin*(Bm.Cm) + D*xin, A_log dead.
#define BB      512
#define DMODEL  512
#define DSTATE  128
#define DINNER  1024
#define DTRANK  32
#define HIDDEN  256
#define XDBL_W  (DTRANK + 2*DSTATE)   // 288

// -------- scratch (no allocations allowed; __device__ globals) --------
__device__ float g_xin [BB*DINNER];
__device__ float g_zsil[BB*DINNER];
__device__ float g_xdbl[BB*XDBL_W];
__device__ float g_y   [BB*DINNER];
__device__ float g_out1[BB*DMODEL];
__device__ float g_h1  [BB*HIDDEN];

__device__ __forceinline__ float siluf(float x) { return x / (1.f + __expf(-x)); }

__device__ __forceinline__ void mma_tf32(float c[4],
                                         unsigned a0, unsigned a1, unsigned a2, unsigned a3,
                                         unsigned b0, unsigned b1)
{
    asm volatile(
        "mma.sync.aligned.m16n8k8.row.col.f32.tf32.tf32.f32 "
        "{%0,%1,%2,%3}, {%4,%5,%6,%7}, {%8,%9}, {%0,%1,%2,%3};"
        : "+f"(c[0]), "+f"(c[1]), "+f"(c[2]), "+f"(c[3])
        : "r"(a0), "r"(a1), "r"(a2), "r"(a3), "r"(b0), "r"(b1));
}

__device__ __forceinline__ void cp16(void* smem, const void* gmem)
{
    unsigned sa = (unsigned)__cvta_generic_to_shared(smem);
    asm volatile("cp.async.cg.shared.global [%0], [%1], 16;" :: "r"(sa), "l"(gmem));
}

// ---------------------------------------------------------------------
// cp.async double-buffered tf32 GEMM: C[M,N] = A[M,K] @ W[N,K]^T.
// BK=32, 256 threads = 8 warps arranged WM x WN, WM = BM/16.
// Raw fp32 bits fed to mma.tf32 (hw truncation; margin is huge).
// MODE 0: plain store
// MODE 1: + bias(aux0), leaky-relu 0.1
// MODE 2: in_proj split (n<DINNER -> silu(conv); else silu -> out2)
// MODE 3: inline bc = Bm.Cm; dt = softplus(v+aux0); C=(dt*xin*bc + aux1*xin)*zsil
// ---------------------------------------------------------------------
template<int MODE, int BM, int BN>
__global__ void __launch_bounds__(256)
gemm_cp(const float* __restrict__ A, int lda,
        const float* __restrict__ W,
        float* __restrict__ C,
        int N, int K,
        const float* __restrict__ aux0,
        const float* __restrict__ aux1,
        float* __restrict__ out2)
{
    constexpr int BK    = 32;
    constexpr int LDS   = 36;            // row pad: conflict-free frag LDS, 16B-aligned rows
    constexpr int WM    = BM / 16;       // warps along m
    constexpr int WN    = 8 / WM;        // warps along n
    constexpr int NSPAN = BN / WN;       // n-cols per warp
    constexpr int NT    = NSPAN / 8;     // m16n8 tiles per warp
    constexpr int ARND  = BM / 32;       // float4 cp.async rounds for A
    constexpr int WRND  = BN / 32;

    __shared__ float As[2][BM][LDS];
    __shared__ float Ws[2][BN][LDS];
    __shared__ float sbc[BM];

    const int tid  = threadIdx.x;
    const int lane = tid & 31;
    const int wid  = tid >> 5;
    const int wm   = wid % WM;
    const int wn   = wid / WM;
    const int g    = lane >> 2;          // 0..7
    const int t    = lane & 3;           // 0..3
    const int m0   = blockIdx.y * BM;
    const int n0   = blockIdx.x * BN;

    const int lrow = tid >> 3;           // 0..31
    const int lcol = (tid & 7) * 4;      // 0,4,...,28

    // MODE3: per-row bc = dot(Bm, Cm); A here is g_xdbl (lda = XDBL_W)
    if (MODE == 3) {
        constexpr int RPW = BM / 8;
        #pragma unroll
        for (int rr = 0; rr < RPW; ++rr) {
            const int r = wid * RPW + rr;
            const float* row = &A[(m0 + r) * XDBL_W];
            float v = 0.f;
            #pragma unroll
            for (int i = 0; i < DSTATE / 32; ++i)
                v += row[DTRANK + lane + 32*i] * row[DTRANK + DSTATE + lane + 32*i];
            #pragma unroll
            for (int o = 16; o > 0; o >>= 1) v += __shfl_xor_sync(0xFFFFFFFFu, v, o);
            if (lane == 0) sbc[r] = v;
        }
    }

    const int NK = K / BK;

    auto load_tiles = [&](int kt, int buf) {
        const int k0 = kt * BK;
        #pragma unroll
        for (int r = 0; r < ARND; ++r)
            cp16(&As[buf][lrow + 32*r][lcol], &A[(m0 + lrow + 32*r) * lda + k0 + lcol]);
        #pragma unroll
        for (int r = 0; r < WRND; ++r)
            cp16(&Ws[buf][lrow + 32*r][lcol], &W[(n0 + lrow + 32*r) * K + k0 + lcol]);
    };

    float acc[NT][4] = {};

    load_tiles(0, 0);
    asm volatile("cp.async.commit_group;");

    for (int it = 0; it < NK; ++it) {
        if (it + 1 < NK) {
            load_tiles(it + 1, (it + 1) & 1);
            asm volatile("cp.async.commit_group;");
            asm volatile("cp.async.wait_group 1;");
        } else {
            asm volatile("cp.async.wait_group 0;");
        }
        __syncthreads();

        const int buf = it & 1;
        #pragma unroll
        for (int ks = 0; ks < BK / 8; ++ks) {
            const int kk = ks * 8 + t;
            const int ar = wm * 16 + g;
            unsigned a0 = __float_as_uint(As[buf][ar    ][kk]);
            unsigned a1 = __float_as_uint(As[buf][ar + 8][kk]);
            unsigned a2 = __float_as_uint(As[buf][ar    ][kk + 4]);
            unsigned a3 = __float_as_uint(As[buf][ar + 8][kk + 4]);
            #pragma unroll
            for (int j = 0; j < NT; ++j) {
                const int br = wn * NSPAN + j * 8 + g;
                unsigned b0 = __float_as_uint(Ws[buf][br][kk]);
                unsigned b1 = __float_as_uint(Ws[buf][br][kk + 4]);
                mma_tf32(acc[j], a0, a1, a2, a3, b0, b1);
            }
        }
        __syncthreads();
    }

    // ---- epilogue (float2 pairs: c0,c1 @ (m,nb); c2,c3 @ (m+8,nb)) ----
    #pragma unroll
    for (int j = 0; j < NT; ++j) {
        const int nb = n0 + wn * NSPAN + j * 8 + 2 * t;
        #pragma unroll
        for (int half = 0; half < 2; ++half) {
            const int m  = m0 + wm * 16 + g + 8 * half;
            float v0 = acc[j][2*half + 0];
            float v1 = acc[j][2*half + 1];
            if (MODE == 0) {
                *reinterpret_cast<float2*>(&C[m * N + nb]) = make_float2(v0, v1);
            } else if (MODE == 1) {
                v0 += aux0[nb]; v1 += aux0[nb + 1];
                v0 = (v0 >= 0.f) ? v0 : 0.1f * v0;
                v1 = (v1 >= 0.f) ? v1 : 0.1f * v1;
                *reinterpret_cast<float2*>(&C[m * N + nb]) = make_float2(v0, v1);
            } else if (MODE == 2) {
                if (n0 < DINNER) {   // uniform per CTA (1024 % BN == 0)
                    float c0 = aux0[nb]     + aux1[2*nb + 1]     * v0;
                    float c1 = aux0[nb + 1] + aux1[2*(nb+1) + 1] * v1;
                    *reinterpret_cast<float2*>(&C[m * DINNER + nb]) =
                        make_float2(siluf(c0), siluf(c1));
                } else {
                    *reinterpret_cast<float2*>(&out2[m * DINNER + nb - DINNER]) =
                        make_float2(siluf(v0), siluf(v1));
                }
            } else { // MODE 3
                v0 += aux0[nb]; v1 += aux0[nb + 1];
                float dt0 = (v0 > 20.f) ? v0 : log1pf(__expf(v0));
                float dt1 = (v1 > 20.f) ? v1 : log1pf(__expf(v1));
                float2 xv = *reinterpret_cast<const float2*>(&g_xin [m * DINNER + nb]);
                float2 zv = *reinterpret_cast<const float2*>(&g_zsil[m * DINNER + nb]);
                float bc  = sbc[m - m0];
                float y0 = (dt0 * xv.x * bc + aux1[nb]     * xv.x) * zv.x;
                float y1 = (dt1 * xv.y * bc + aux1[nb + 1] * xv.y) * zv.y;
                *reinterpret_cast<float2*>(&C[m * DINNER + nb]) = make_float2(y0, y1);
            }
        }
    }
}

// out[b] = sigmoid( dot(h1[b], fc5_w) + fc5_b )
__global__ void fc5_kernel(const float* __restrict__ w,
                           const float* __restrict__ bias,
                           float* __restrict__ out)
{
    const int b = blockIdx.x;
    const int t = threadIdx.x;  // 256
    float v = g_h1[b * HIDDEN + t] * w[t];
    #pragma unroll
    for (int o = 16; o > 0; o >>= 1) v += __shfl_xor_sync(0xFFFFFFFFu, v, o);
    __shared__ float ws[8];
    if ((t & 31) == 0) ws[t >> 5] = v;
    __syncthreads();
    if (t == 0) {
        float s = bias[0];
        #pragma unroll
        for (int i = 0; i < 8; i++) s += ws[i];
        out[b] = 1.f / (1.f + __expf(-s));
    }
}

extern "C" void kernel_launch(void* const* d_in, const int* in_sizes, int n_in,
                              void* d_out, int out_size)
{
    const float* x         = (const float*)d_in[0];
    const float* in_proj_w = (const float*)d_in[1];
    const float* conv_w    = (const float*)d_in[2];
    const float* conv_b    = (const float*)d_in[3];
    const float* x_proj_w  = (const float*)d_in[4];
    const float* dt_proj_w = (const float*)d_in[5];
    const float* dt_proj_b = (const float*)d_in[6];
    // d_in[7] = A_log: dead (h0 = 0, L = 1)
    const float* Dp        = (const float*)d_in[8];
    const float* out_projw = (const float*)d_in[9];
    const float* fc1_w     = (const float*)d_in[10];
    const float* fc1_b     = (const float*)d_in[11];
    const float* fc5_w     = (const float*)d_in[12];
    const float* fc5_b     = (const float*)d_in[13];
    float* out = (float*)d_out;

    float *xin, *zsil, *xdbl, *y, *out1, *h1;
    cudaGetSymbolAddress((void**)&xin,  g_xin);
    cudaGetSymbolAddress((void**)&zsil, g_zsil);
    cudaGetSymbolAddress((void**)&xdbl, g_xdbl);
    cudaGetSymbolAddress((void**)&y,    g_y);
    cudaGetSymbolAddress((void**)&out1, g_out1);
    cudaGetSymbolAddress((void**)&h1,   g_h1);

    const dim3 blk(256);
    // 1. in_proj (N=2048,K=512) + conv + silu split        [grid 32x8 = 256]
    gemm_cp<2, 64, 64><<<dim3(2048/64, BB/64), blk>>>(x, DMODEL, in_proj_w, xin,
                                                      2*DINNER, DMODEL, conv_b, conv_w, zsil);
    // 2. x_proj (N=288,K=1024) -> xdbl                     [grid 9x16 = 144]
    gemm_cp<0, 32, 32><<<dim3(XDBL_W/32, BB/32), blk>>>(xin, DINNER, x_proj_w, xdbl,
                                                        XDBL_W, DINNER, nullptr, nullptr, nullptr);
    // 3. dt_proj (N=1024,K=32) + inline bc + y             [grid 16x16 = 256]
    gemm_cp<3, 32, 64><<<dim3(DINNER/64, BB/32), blk>>>(xdbl, XDBL_W, dt_proj_w, y,
                                                        DINNER, DTRANK, dt_proj_b, Dp, nullptr);
    // 4. out_proj (N=512,K=1024) -> out1                   [grid 16x16 = 256]
    gemm_cp<0, 32, 32><<<dim3(DMODEL/32, BB/32), blk>>>(y, DINNER, out_projw, out1,
                                                        DMODEL, DINNER, nullptr, nullptr, nullptr);
    // 5. fc1 (N=256,K=512) + bias + leaky -> h1            [grid 8x16 = 128]
    gemm_cp<1, 32, 32><<<dim3(HIDDEN/32, BB/32), blk>>>(out1, DMODEL, fc1_w, h1,
                                                        HIDDEN, DMODEL, fc1_b, nullptr, nullptr);
    // 6. fc5 + sigmoid -> out (B,1)
    fc5_kernel<<<BB, 256>>>(fc5_w, fc5_b, out);
}